// round 1
// baseline (speedup 1.0000x reference)
#include <cuda_runtime.h>

#define NA 300000
#define NT 300000
#define HID 32
#define NH 4
#define E_IN 1000000
#define E_OUT 1000000
#define E_SP 500000
#define NLAYERS 4

// ---------------- device scratch (no allocs allowed) ----------------
__device__ float g_xa[NA * HID];
__device__ float g_xt[NT * HID];
__device__ float g_ha[NA * HID];
__device__ float g_ht[NT * HID];
__device__ float g_asrc0[NA * NH];
__device__ float g_adst0[NT * NH];
__device__ float g_asrc1[NT * NH];
__device__ float g_adst1[NA * NH];
__device__ float g_asrc2[NT * NH];
__device__ float g_adst2[NT * NH];
__device__ float g_den0[NT * NH];
__device__ float g_den1[NA * NH];
__device__ float g_den2[NT * NH];
__device__ float g_ex[E_IN * NH];          // reused per relation
__device__ float g_agg0[NT * HID];
__device__ float g_agg1[NA * HID];
__device__ float g_agg2[NT * HID];
__device__ float g_sacc[2 * 32 * 32];      // padded: lane j at [j*32]
__device__ float g_attn[2];

// ---------------- helpers ----------------
__device__ __forceinline__ float wsum32(float v) {
    #pragma unroll
    for (int o = 16; o > 0; o >>= 1) v += __shfl_xor_sync(0xffffffffu, v, o);
    return v;
}

__device__ __forceinline__ void red_add_v4(float* addr, float4 v) {
    asm volatile("red.global.add.v4.f32 [%0], {%1,%2,%3,%4};"
                 :: "l"(addr), "f"(v.x), "f"(v.y), "f"(v.z), "f"(v.w)
                 : "memory");
}

// ---------------- kernels ----------------

// out[n,j] = relu(sum_k x[n,k]*W[k,j] + b[j]);  warp per node
__global__ void enc_kernel(const float* __restrict__ x, const float* __restrict__ W,
                           const float* __restrict__ b, float* __restrict__ out,
                           int n, int K) {
    int lane = threadIdx.x & 31;
    int node = blockIdx.x * (blockDim.x >> 5) + (threadIdx.x >> 5);
    if (node >= n) return;
    float acc = b[lane];
    const float* xr = x + (size_t)node * K;
    for (int k = 0; k < K; k++) acc += xr[k] * W[k * 32 + lane];
    out[node * 32 + lane] = fmaxf(acc, 0.f);
}

// h[n,j] = x[n]@W + b; also up to 4 per-head attention dots (head = lane>>3)
__global__ void proj_kernel(const float* __restrict__ x, const float* __restrict__ W,
                            const float* __restrict__ b, float* __restrict__ hout, int n,
                            const float* __restrict__ a0, float* __restrict__ o0,
                            const float* __restrict__ a1, float* __restrict__ o1,
                            const float* __restrict__ a2, float* __restrict__ o2,
                            const float* __restrict__ a3, float* __restrict__ o3,
                            int natt) {
    int lane = threadIdx.x & 31;
    int node = blockIdx.x * (blockDim.x >> 5) + (threadIdx.x >> 5);
    if (node >= n) return;
    float xv = x[node * 32 + lane];
    float acc = b[lane];
    #pragma unroll
    for (int k = 0; k < 32; k++) {
        float a = __shfl_sync(0xffffffffu, xv, k);
        acc += a * W[k * 32 + lane];
    }
    hout[node * 32 + lane] = acc;
    int head = lane >> 3;
    #define DOT8(av, ov)                                                   \
        {                                                                  \
            float p = acc * (av)[lane];                                    \
            p += __shfl_xor_sync(0xffffffffu, p, 1);                       \
            p += __shfl_xor_sync(0xffffffffu, p, 2);                       \
            p += __shfl_xor_sync(0xffffffffu, p, 4);                       \
            if ((lane & 7) == 0) (ov)[node * 4 + head] = p;                \
        }
    if (natt > 0) DOT8(a0, o0);
    if (natt > 1) DOT8(a1, o1);
    if (natt > 2) DOT8(a2, o2);
    if (natt > 3) DOT8(a3, o3);
    #undef DOT8
}

// thread per edge: ex = exp(leaky_relu(asrc[si]+adst[di])), atomic-add into den[di]
__global__ void edge_pass1(const int* __restrict__ ei, int E,
                           const float* __restrict__ asrc, const float* __restrict__ adst,
                           float* __restrict__ exbuf, float* __restrict__ den) {
    int e = blockIdx.x * blockDim.x + threadIdx.x;
    if (e >= E) return;
    int si = ei[e];
    int di = ei[E + e];
    float4 s = *(const float4*)(asrc + si * 4);
    float4 d = *(const float4*)(adst + di * 4);
    float4 ex;
    float v;
    v = s.x + d.x; if (v < 0.f) v *= 0.2f; ex.x = expf(v);
    v = s.y + d.y; if (v < 0.f) v *= 0.2f; ex.y = expf(v);
    v = s.z + d.z; if (v < 0.f) v *= 0.2f; ex.z = expf(v);
    v = s.w + d.w; if (v < 0.f) v *= 0.2f; ex.w = expf(v);
    *(float4*)(exbuf + e * 4) = ex;
    red_add_v4(den + di * 4, ex);
}

// 8 threads per edge (one float4 chunk each): msg = w * hs[si], scatter-add to agg[di]
__global__ void edge_pass2(const int* __restrict__ ei, int E,
                           const float* __restrict__ exbuf, const float* __restrict__ den,
                           const float* __restrict__ hs, float* __restrict__ agg) {
    int t = blockIdx.x * blockDim.x + threadIdx.x;
    int e = t >> 3;
    if (e >= E) return;
    int c = t & 7;           // chunk 0..7
    int head = c >> 1;
    int si = ei[e];
    int di = ei[E + e];
    float w = exbuf[e * 4 + head] / (den[di * 4 + head] + 1e-16f);
    float4 hv = *(const float4*)(hs + si * 32 + c * 4);
    float4 m = make_float4(hv.x * w, hv.y * w, hv.z * w, hv.w * w);
    red_add_v4(agg + di * 32 + c * 4, m);
}

// semantic-attention score partials: acc[j*32] += sum_n tanh(relu(agg[n])@kw + kb)[j]
__global__ void score_kernel(const float* __restrict__ agg, const float* __restrict__ kw,
                             const float* __restrict__ kb, float* __restrict__ acc, int n) {
    int lane = threadIdx.x & 31;
    int nwarp = (blockDim.x >> 5) * gridDim.x;
    int widx = blockIdx.x * (blockDim.x >> 5) + (threadIdx.x >> 5);
    float kbl = kb[lane];
    float tsum = 0.f;
    for (int node = widx; node < n; node += nwarp) {
        float xv = fmaxf(agg[node * 32 + lane], 0.f);
        float a = kbl;
        #pragma unroll
        for (int k = 0; k < 32; k++) {
            float s = __shfl_sync(0xffffffffu, xv, k);
            a += s * kw[k * 32 + lane];
        }
        tsum += tanhf(a);
    }
    __shared__ float s[32];
    if (threadIdx.x < 32) s[threadIdx.x] = 0.f;
    __syncthreads();
    atomicAdd(&s[lane], tsum);
    __syncthreads();
    if (threadIdx.x < 32) atomicAdd(&acc[threadIdx.x * 32], s[threadIdx.x]);
}

// softmax over the 2 tx-relation scores
__global__ void score_fin(const float* __restrict__ acc0, const float* __restrict__ acc2,
                          const float* __restrict__ q, float* __restrict__ attn, float invN) {
    int j = threadIdx.x;  // 32 threads
    float s0 = q[j] * acc0[j * 32] * invN;
    float s2 = q[j] * acc2[j * 32] * invN;
    s0 = wsum32(s0);
    s2 = wsum32(s2);
    if (j == 0) {
        float m = fmaxf(s0, s2);
        float e0 = expf(s0 - m), e2 = expf(s2 - m);
        float inv = 1.f / (e0 + e2);
        attn[0] = e0 * inv;
        attn[1] = e2 * inv;
    }
}

__global__ void upd_tx_kernel(const float* __restrict__ agg0, const float* __restrict__ agg2,
                              const float* __restrict__ attn, float* __restrict__ xt,
                              const float* __restrict__ g, const float* __restrict__ b, int n) {
    int lane = threadIdx.x & 31;
    int node = blockIdx.x * (blockDim.x >> 5) + (threadIdx.x >> 5);
    if (node >= n) return;
    float a0 = attn[0], a2 = attn[1];
    int i = node * 32 + lane;
    float v = a0 * fmaxf(agg0[i], 0.f) + a2 * fmaxf(agg2[i], 0.f);
    v = fmaxf(v, 0.f) + xt[i];
    float m = wsum32(v) * (1.f / 32.f);
    float c = v - m;
    float var = wsum32(c * c) * (1.f / 32.f);
    xt[i] = c * rsqrtf(var + 1e-5f) * g[lane] + b[lane];
}

__global__ void upd_addr_kernel(const float* __restrict__ agg1, float* __restrict__ xa,
                                const float* __restrict__ g, const float* __restrict__ b, int n) {
    int lane = threadIdx.x & 31;
    int node = blockIdx.x * (blockDim.x >> 5) + (threadIdx.x >> 5);
    if (node >= n) return;
    int i = node * 32 + lane;
    float v = fmaxf(agg1[i], 0.f) + xa[i];
    float m = wsum32(v) * (1.f / 32.f);
    float c = v - m;
    float var = wsum32(c * c) * (1.f / 32.f);
    xa[i] = c * rsqrtf(var + 1e-5f) * g[lane] + b[lane];
}

__global__ void head_kernel(const float* __restrict__ xa, const float* __restrict__ w,
                            const float* __restrict__ b, float* __restrict__ out, int n) {
    int lane = threadIdx.x & 31;
    int node = blockIdx.x * (blockDim.x >> 5) + (threadIdx.x >> 5);
    if (node >= n) return;
    float v = xa[node * 32 + lane];
    float s0 = wsum32(v * w[lane * 2 + 0]);
    float s1 = wsum32(v * w[lane * 2 + 1]);
    if (lane == 0) {
        out[node * 2 + 0] = s0 + b[0];
        out[node * 2 + 1] = s1 + b[1];
    }
}

// ---------------- launch ----------------
extern "C" void kernel_launch(void* const* d_in, const int* in_sizes, int n_in,
                              void* d_out, int out_size) {
    const float* x_addr  = (const float*)d_in[0];
    const float* x_tx    = (const float*)d_in[1];
    const int*   ei_in   = (const int*)d_in[2];
    const int*   ei_out  = (const int*)d_in[3];
    const int*   ei_sp   = (const int*)d_in[4];
    const float* enc_w_a = (const float*)d_in[5];
    const float* enc_b_a = (const float*)d_in[6];
    const float* enc_w_t = (const float*)d_in[7];
    const float* enc_b_t = (const float*)d_in[8];
    const float* ln_a_g  = (const float*)d_in[9];
    const float* ln_a_b  = (const float*)d_in[10];
    const float* ln_t_g  = (const float*)d_in[11];
    const float* ln_t_b  = (const float*)d_in[12];
    const float* pw_a    = (const float*)d_in[13];
    const float* pb_a    = (const float*)d_in[14];
    const float* pw_t    = (const float*)d_in[15];
    const float* pb_t    = (const float*)d_in[16];
    const float* att_src = (const float*)d_in[17];
    const float* att_dst = (const float*)d_in[18];
    const float* klin_w  = (const float*)d_in[19];
    const float* klin_b  = (const float*)d_in[20];
    const float* qv      = (const float*)d_in[21];
    const float* lin_w   = (const float*)d_in[22];
    const float* lin_b   = (const float*)d_in[23];
    float* out = (float*)d_out;

    float *xa, *xt, *ha, *ht;
    float *asrc0, *adst0, *asrc1, *adst1, *asrc2, *adst2;
    float *den0, *den1, *den2, *ex, *agg0, *agg1, *agg2, *sacc, *attn;
    cudaGetSymbolAddress((void**)&xa, g_xa);
    cudaGetSymbolAddress((void**)&xt, g_xt);
    cudaGetSymbolAddress((void**)&ha, g_ha);
    cudaGetSymbolAddress((void**)&ht, g_ht);
    cudaGetSymbolAddress((void**)&asrc0, g_asrc0);
    cudaGetSymbolAddress((void**)&adst0, g_adst0);
    cudaGetSymbolAddress((void**)&asrc1, g_asrc1);
    cudaGetSymbolAddress((void**)&adst1, g_adst1);
    cudaGetSymbolAddress((void**)&asrc2, g_asrc2);
    cudaGetSymbolAddress((void**)&adst2, g_adst2);
    cudaGetSymbolAddress((void**)&den0, g_den0);
    cudaGetSymbolAddress((void**)&den1, g_den1);
    cudaGetSymbolAddress((void**)&den2, g_den2);
    cudaGetSymbolAddress((void**)&ex, g_ex);
    cudaGetSymbolAddress((void**)&agg0, g_agg0);
    cudaGetSymbolAddress((void**)&agg1, g_agg1);
    cudaGetSymbolAddress((void**)&agg2, g_agg2);
    cudaGetSymbolAddress((void**)&sacc, g_sacc);
    cudaGetSymbolAddress((void**)&attn, g_attn);

    const int WPB = 8;               // warps (nodes) per block
    const int TPB = WPB * 32;        // 256 threads
    dim3 gridA((NA + WPB - 1) / WPB), gridT((NT + WPB - 1) / WPB), blk(TPB);

    // encoders
    enc_kernel<<<gridA, blk>>>(x_addr, enc_w_a, enc_b_a, xa, NA, 53);
    enc_kernel<<<gridT, blk>>>(x_tx, enc_w_t, enc_b_t, xt, NT, 6);

    for (int l = 0; l < NLAYERS; l++) {
        const float* PWA = pw_a + l * 32 * 32;
        const float* PBA = pb_a + l * 32;
        const float* PWT = pw_t + l * 32 * 32;
        const float* PBT = pb_t + l * 32;
        const float* AS = att_src + l * 3 * 32;  // [3][32]
        const float* AD = att_dst + l * 3 * 32;
        const float* KW = klin_w + l * 32 * 32;
        const float* KB = klin_b + l * 32;
        const float* Q  = qv + l * 32;

        // projections + attention node terms
        proj_kernel<<<gridA, blk>>>(xa, PWA, PBA, ha, NA,
                                    AS + 0 * 32, asrc0,   // rel0 src = addr
                                    AD + 1 * 32, adst1,   // rel1 dst = addr
                                    nullptr, nullptr, nullptr, nullptr, 2);
        proj_kernel<<<gridT, blk>>>(xt, PWT, PBT, ht, NT,
                                    AD + 0 * 32, adst0,   // rel0 dst = tx
                                    AS + 1 * 32, asrc1,   // rel1 src = tx
                                    AS + 2 * 32, asrc2,   // rel2 src = tx
                                    AD + 2 * 32, adst2, 4);

        cudaMemsetAsync(den0, 0, (size_t)NT * NH * sizeof(float));
        cudaMemsetAsync(den1, 0, (size_t)NA * NH * sizeof(float));
        cudaMemsetAsync(den2, 0, (size_t)NT * NH * sizeof(float));
        cudaMemsetAsync(agg0, 0, (size_t)NT * HID * sizeof(float));
        cudaMemsetAsync(agg1, 0, (size_t)NA * HID * sizeof(float));
        cudaMemsetAsync(agg2, 0, (size_t)NT * HID * sizeof(float));
        cudaMemsetAsync(sacc, 0, 2 * 32 * 32 * sizeof(float));

        // relation 0: addr -> tx
        edge_pass1<<<(E_IN + 255) / 256, 256>>>(ei_in, E_IN, asrc0, adst0, ex, den0);
        edge_pass2<<<((size_t)E_IN * 8 + 255) / 256, 256>>>(ei_in, E_IN, ex, den0, ha, agg0);
        // relation 1: tx -> addr
        edge_pass1<<<(E_OUT + 255) / 256, 256>>>(ei_out, E_OUT, asrc1, adst1, ex, den1);
        edge_pass2<<<((size_t)E_OUT * 8 + 255) / 256, 256>>>(ei_out, E_OUT, ex, den1, ht, agg1);
        // relation 2: tx -> tx
        edge_pass1<<<(E_SP + 255) / 256, 256>>>(ei_sp, E_SP, asrc2, adst2, ex, den2);
        edge_pass2<<<((size_t)E_SP * 8 + 255) / 256, 256>>>(ei_sp, E_SP, ex, den2, ht, agg2);

        // semantic attention over the two tx relations
        score_kernel<<<1024, 256>>>(agg0, KW, KB, sacc, NT);
        score_kernel<<<1024, 256>>>(agg2, KW, KB, sacc + 1024, NT);
        score_fin<<<1, 32>>>(sacc, sacc + 1024, Q, attn, 1.0f / (float)NT);

        // residual + layernorm
        upd_tx_kernel<<<gridT, blk>>>(agg0, agg2, attn, xt, ln_t_g, ln_t_b, NT);
        upd_addr_kernel<<<gridA, blk>>>(agg1, xa, ln_a_g, ln_a_b, NA);
    }

    head_kernel<<<gridA, blk>>>(xa, lin_w, lin_b, out, NA);
}